// round 8
// baseline (speedup 1.0000x reference)
#include <cuda_runtime.h>
#include <math.h>

#define NN 20000
#define EE 640000
#define HH 128
#define LAYER 2
#define DSCALE 10.0f
#define DITHER 1e-4f

// per-node accumulator: [den0, den1, t0,t1,t2, R00..R22, pad, pad] = 16 floats
__device__ float g_acc[NN * 16];

// ---------- f32x2 helpers ----------
__device__ __forceinline__ void fma2(unsigned long long &acc, unsigned long long a, unsigned long long b) {
    asm("fma.rn.f32x2 %0, %1, %2, %0;" : "+l"(acc) : "l"(a), "l"(b));
}
__device__ __forceinline__ unsigned long long pack2(float x) {
    unsigned long long r; asm("mov.b64 %0, {%1, %1};" : "=l"(r) : "f"(x)); return r;
}
__device__ __forceinline__ float2 unpk(unsigned long long v) {
    float2 r; asm("mov.b64 {%0, %1}, %2;" : "=f"(r.x), "=f"(r.y) : "l"(v)); return r;
}

// ---------- jax threefry2x32 (20 rounds) ----------
__device__ __forceinline__ void tf_round(unsigned &x0, unsigned &x1, int r) {
    x0 += x1; x1 = __funnelshift_l(x1, x1, r); x1 ^= x0;
}
__device__ __forceinline__ void threefry(unsigned k0, unsigned k1, unsigned c0, unsigned c1,
                                         unsigned &o0, unsigned &o1) {
    unsigned ks2 = k0 ^ k1 ^ 0x1BD11BDAu;
    unsigned x0 = c0 + k0, x1 = c1 + k1;
    tf_round(x0,x1,13); tf_round(x0,x1,15); tf_round(x0,x1,26); tf_round(x0,x1,6);
    x0 += k1;  x1 += ks2 + 1u;
    tf_round(x0,x1,17); tf_round(x0,x1,29); tf_round(x0,x1,16); tf_round(x0,x1,24);
    x0 += ks2; x1 += k0 + 2u;
    tf_round(x0,x1,13); tf_round(x0,x1,15); tf_round(x0,x1,26); tf_round(x0,x1,6);
    x0 += k0;  x1 += k1 + 3u;
    tf_round(x0,x1,17); tf_round(x0,x1,29); tf_round(x0,x1,16); tf_round(x0,x1,24);
    x0 += k1;  x1 += ks2 + 4u;
    tf_round(x0,x1,13); tf_round(x0,x1,15); tf_round(x0,x1,26); tf_round(x0,x1,6);
    x0 += ks2; x1 += k0 + 5u;
    o0 = x0; o1 = x1;
}

// jax PARTITIONABLE threefry (default since 0.4.36):
//   random_bits (32-bit): per-element counter (hi=0, lo=idx); bits = o0 ^ o1
//   split: fold-like; subkey i = (o0, o1) of threefry(key, (0, i))
//   fold_in: unchanged; f = threefry(key, (0, data))
__device__ __forceinline__ unsigned tf_bits(unsigned k0, unsigned k1, unsigned idx) {
    unsigned o0, o1;
    threefry(k0, k1, 0u, idx, o0, o1);
    return o0 ^ o1;
}
// layer-2 keys: base=(0,42); f = TF(base,(0,2)); k1 = TF(f,(0,0)); k2 = TF(f,(0,1))
__device__ __forceinline__ void derive_keys(unsigned &k1a, unsigned &k1b,
                                            unsigned &k2a, unsigned &k2b) {
    unsigned f0, f1;
    threefry(0u, 42u, 0u, 2u, f0, f1);
    threefry(f0, f1, 0u, 0u, k1a, k1b);
    threefry(f0, f1, 0u, 1u, k2a, k2b);
}
// jax: u01 = bitcast((bits>>9)|0x3f800000)-1; r = max(lo, u01*(hi-lo)+lo); sqrt(2)*erfinv(r)
__device__ __forceinline__ float bits_to_normal(unsigned bits) {
    const float lo = -0.99999994f;
    float u01 = __uint_as_float((bits >> 9) | 0x3f800000u) - 1.0f;
    float r = fmaxf(lo, fmaf(u01, 2.0f, lo));
    return 1.41421356f * erfinvf(r);
}

// ---------- fp32 polar factor with reference's det fix (edges) ----------
__device__ void polar3(const float M[9], float R[9]) {
    float X[9];
#pragma unroll
    for (int i = 0; i < 9; ++i) X[i] = M[i];
#pragma unroll
    for (int it = 0; it < 9; ++it) {
        float c0 = X[4]*X[8] - X[5]*X[7];
        float c1 = X[5]*X[6] - X[3]*X[8];
        float c2 = X[3]*X[7] - X[4]*X[6];
        float c3 = X[2]*X[7] - X[1]*X[8];
        float c4 = X[0]*X[8] - X[2]*X[6];
        float c5 = X[1]*X[6] - X[0]*X[7];
        float c6 = X[1]*X[5] - X[2]*X[4];
        float c7 = X[2]*X[3] - X[0]*X[5];
        float c8 = X[0]*X[4] - X[1]*X[3];
        float det = X[0]*c0 + X[1]*c1 + X[2]*c2;
        float rdet = (fabsf(det) > 1e-30f) ? (1.0f / det) : 0.0f;
        float g = 1.0f;
        if (it < 4) {
            float a = X[0]*X[0]+X[1]*X[1]+X[2]*X[2]+X[3]*X[3]+X[4]*X[4]
                    + X[5]*X[5]+X[6]*X[6]+X[7]*X[7]+X[8]*X[8];
            float b = (c0*c0+c1*c1+c2*c2+c3*c3+c4*c4+c5*c5+c6*c6+c7*c7+c8*c8) * rdet * rdet;
            g = sqrtf(sqrtf(b / (a + 1e-30f)));
            g = fminf(fmaxf(g, 1e-5f), 1e5f);
        }
        float ha = 0.5f * g;
        float hb = 0.5f * rdet / g;
        X[0]=ha*X[0]+hb*c0; X[1]=ha*X[1]+hb*c1; X[2]=ha*X[2]+hb*c2;
        X[3]=ha*X[3]+hb*c3; X[4]=ha*X[4]+hb*c4; X[5]=ha*X[5]+hb*c5;
        X[6]=ha*X[6]+hb*c6; X[7]=ha*X[7]+hb*c7; X[8]=ha*X[8]+hb*c8;
    }
    float d = X[0]*(X[4]*X[8]-X[5]*X[7]) - X[1]*(X[3]*X[8]-X[5]*X[6]) + X[2]*(X[3]*X[7]-X[4]*X[6]);
#pragma unroll
    for (int i = 0; i < 9; ++i) R[i] = X[i];
    R[2] *= d; R[5] *= d; R[8] *= d;
}

// ---------- fp64 polar factor (nodes; 20000 only, precision hedge) ----------
__device__ void polar3d(const double M[9], float R[9]) {
    double X[9];
#pragma unroll
    for (int i = 0; i < 9; ++i) X[i] = M[i];
#pragma unroll
    for (int it = 0; it < 9; ++it) {
        double c0 = X[4]*X[8] - X[5]*X[7];
        double c1 = X[5]*X[6] - X[3]*X[8];
        double c2 = X[3]*X[7] - X[4]*X[6];
        double c3 = X[2]*X[7] - X[1]*X[8];
        double c4 = X[0]*X[8] - X[2]*X[6];
        double c5 = X[1]*X[6] - X[0]*X[7];
        double c6 = X[1]*X[5] - X[2]*X[4];
        double c7 = X[2]*X[3] - X[0]*X[5];
        double c8 = X[0]*X[4] - X[1]*X[3];
        double det = X[0]*c0 + X[1]*c1 + X[2]*c2;
        double rdet = (fabs(det) > 1e-280) ? (1.0 / det) : 0.0;
        double g = 1.0;
        if (it < 4) {
            double a = X[0]*X[0]+X[1]*X[1]+X[2]*X[2]+X[3]*X[3]+X[4]*X[4]
                     + X[5]*X[5]+X[6]*X[6]+X[7]*X[7]+X[8]*X[8];
            double b = (c0*c0+c1*c1+c2*c2+c3*c3+c4*c4+c5*c5+c6*c6+c7*c7+c8*c8) * rdet * rdet;
            g = sqrt(sqrt(b / (a + 1e-300)));
            g = fmin(fmax(g, 1e-8), 1e8);
        }
        double ha = 0.5 * g;
        double hb = 0.5 * rdet / g;
        X[0]=ha*X[0]+hb*c0; X[1]=ha*X[1]+hb*c1; X[2]=ha*X[2]+hb*c2;
        X[3]=ha*X[3]+hb*c3; X[4]=ha*X[4]+hb*c4; X[5]=ha*X[5]+hb*c5;
        X[6]=ha*X[6]+hb*c6; X[7]=ha*X[7]+hb*c7; X[8]=ha*X[8]+hb*c8;
    }
    double d = X[0]*(X[4]*X[8]-X[5]*X[7]) - X[1]*(X[3]*X[8]-X[5]*X[6]) + X[2]*(X[3]*X[7]-X[4]*X[6]);
#pragma unroll
    for (int i = 0; i < 9; ++i) R[i] = (float)X[i];
    R[2] *= (float)d; R[5] *= (float)d; R[8] *= (float)d;
}

__global__ void zero_acc_kernel() {
    int i = blockIdx.x * 256 + threadIdx.x;
    if (i < NN * 16) g_acc[i] = 0.0f;
}

// ---------- edge scalar tail ----------
__device__ __forceinline__ void do_edge(
    int e, const unsigned long long acc[8], const float* sB,
    unsigned k1a, unsigned k1b,
    const int* __restrict__ eidx, const float* __restrict__ R, const float* __restrict__ t)
{
    float out[16];
#pragma unroll
    for (int m = 0; m < 8; ++m) {
        float2 v = unpk(acc[m]);
        out[2*m]   = v.x + sB[2*m];
        out[2*m+1] = v.y + sB[2*m+1];
    }
    float s0 = 1.0f / (1.0f + expf(-out[0]));
    float s1 = 1.0f / (1.0f + expf(-out[1]));
    int src = eidx[e];
    int dst = eidx[EE + e];
    float Rs[9], Rd[9];
#pragma unroll
    for (int i = 0; i < 9; ++i) { Rs[i] = R[src*9 + i]; Rd[i] = R[dst*9 + i]; }
    float dt0 = t[src*3+0] - t[dst*3+0];
    float dt1 = t[src*3+1] - t[dst*3+1];
    float dt2 = t[src*3+2] - t[dst*3+2];

    // dither noise, partitionable stream: element idx = e*9 + j
    float nz[9];
#pragma unroll
    for (int j = 0; j < 9; ++j)
        nz[j] = bits_to_normal(tf_bits(k1a, k1b, (unsigned)e * 9u + (unsigned)j));

    // q = s0 * (Rd^T Rs) + (1-s0) * Lq + eps*noise
    float q[9];
#pragma unroll
    for (int i = 0; i < 3; ++i)
#pragma unroll
        for (int k = 0; k < 3; ++k) {
            float rji = Rd[0*3+i]*Rs[0*3+k] + Rd[1*3+i]*Rs[1*3+k] + Rd[2*3+i]*Rs[2*3+k];
            q[i*3+k] = s0 * rji + (1.0f - s0) * out[2 + i*3 + k] + DITHER * nz[i*3+k];
        }
    float tts[3];
#pragma unroll
    for (int i = 0; i < 3; ++i) {
        float tji = Rd[0*3+i]*dt0 + Rd[1*3+i]*dt1 + Rd[2*3+i]*dt2;
        tts[i] = s1 * tji + (1.0f - s1) * DSCALE * out[11 + i];
    }
    float Rts[9];
    polar3(q, Rts);

    float e0l = expf(out[14]);   // softmax weight for t (no max-shift; logits ~N(0,1))
    float e1l = expf(out[15]);   // softmax weight for R

    float* ap = g_acc + (size_t)src * 16;
    atomicAdd(ap + 0, e0l);
    atomicAdd(ap + 1, e1l);
#pragma unroll
    for (int i = 0; i < 3; ++i) {
        float tp = t[dst*3+i] + Rd[i*3+0]*tts[0] + Rd[i*3+1]*tts[1] + Rd[i*3+2]*tts[2];
        atomicAdd(ap + 2 + i, e0l * tp);
    }
#pragma unroll
    for (int i = 0; i < 3; ++i)
#pragma unroll
        for (int k = 0; k < 3; ++k) {
            float rp = Rd[i*3+0]*Rts[0*3+k] + Rd[i*3+1]*Rts[1*3+k] + Rd[i*3+2]*Rts[2*3+k];
            atomicAdd(ap + 5 + i*3 + k, e1l * rp);
        }
}

// ---------- edge kernel: 512 consecutive edges per block of 256 threads ----------
__global__ void __launch_bounds__(256) edge_kernel(
    const float* __restrict__ emb, const int* __restrict__ eidx,
    const float* __restrict__ R,  const float* __restrict__ t,
    const float* __restrict__ Ws, const float* __restrict__ bs_,
    const float* __restrict__ Wq, const float* __restrict__ bq_,
    const float* __restrict__ Wt, const float* __restrict__ bt_,
    const float* __restrict__ Wl, const float* __restrict__ bl_)
{
    __shared__ float sW[HH][16];     // fused weights, cols: [Ws(2)|Wq(9)|Wt(3)|Wl(2)]
    __shared__ float sB[16];
    __shared__ float sS[16][514];    // transposed emb chunk

    const int tid = threadIdx.x;
    for (int i = tid; i < HH * 16; i += 256) {
        int h = i >> 4, c = i & 15;
        int hb = LAYER * HH + h;
        float w;
        if (c < 2)       w = Ws[hb*2 + c];
        else if (c < 11) w = Wq[hb*9 + (c - 2)];
        else if (c < 14) w = Wt[hb*3 + (c - 11)];
        else             w = Wl[hb*2 + (c - 14)];
        sW[h][c] = w;
    }
    if (tid < 16) {
        int c = tid; float b;
        if (c < 2)       b = bs_[LAYER*2 + c];
        else if (c < 11) b = bq_[LAYER*9 + c - 2];
        else if (c < 14) b = bt_[LAYER*3 + c - 11];
        else             b = bl_[LAYER*2 + c - 14];
        sB[c] = b;
    }

    const int e0 = blockIdx.x * 512;
    const float4* emb4 = reinterpret_cast<const float4*>(emb);

    unsigned long long accA[8], accB[8];
#pragma unroll
    for (int m = 0; m < 8; ++m) { accA[m] = 0ull; accB[m] = 0ull; }

    for (int c = 0; c < 8; ++c) {              // 8 chunks of 16 H-dims
        __syncthreads();
#pragma unroll
        for (int k = 0; k < 8; ++k) {
            int idx = tid + 256 * k;           // 0..2047 = 512 edges x 4 float4
            int de  = idx >> 2;
            int d4  = idx & 3;
            float4 v = emb4[(size_t)(e0 + de) * 32 + c * 4 + d4];
            int row = d4 * 4;
            sS[row + 0][de] = v.x;
            sS[row + 1][de] = v.y;
            sS[row + 2][de] = v.z;
            sS[row + 3][de] = v.w;
        }
        __syncthreads();
#pragma unroll
        for (int dh = 0; dh < 16; ++dh) {
            int h = c * 16 + dh;
            unsigned long long pa = pack2(sS[dh][tid]);
            unsigned long long pb = pack2(sS[dh][tid + 256]);
            const ulonglong2* wr = reinterpret_cast<const ulonglong2*>(&sW[h][0]);
#pragma unroll
            for (int p = 0; p < 4; ++p) {
                ulonglong2 w = wr[p];
                fma2(accA[2*p],   pa, w.x);
                fma2(accA[2*p+1], pa, w.y);
                fma2(accB[2*p],   pb, w.x);
                fma2(accB[2*p+1], pb, w.y);
            }
        }
    }

    unsigned k1a, k1b, k2a, k2b;
    derive_keys(k1a, k1b, k2a, k2b);

    do_edge(e0 + tid,       accA, sB, k1a, k1b, eidx, R, t);
    do_edge(e0 + tid + 256, accB, sB, k1a, k1b, eidx, R, t);
}

// ---------- node kernel: one warp per node ----------
__global__ void __launch_bounds__(256) node_kernel(
    const float* __restrict__ node_emb,
    const float* __restrict__ Wa, const float* __restrict__ ba,
    float* __restrict__ X)
{
    int n = blockIdx.x * 8 + (threadIdx.x >> 5);
    int l = threadIdx.x & 31;
    const float4* em4 = reinterpret_cast<const float4*>(node_emb);
    float4 em = em4[(size_t)n * 32 + l];

    float p[12];
#pragma unroll
    for (int c = 0; c < 12; ++c) p[c] = 0.0f;
#pragma unroll
    for (int j = 0; j < 4; ++j) {
        int h = 4 * l + j;
        const float* wrow = Wa + (size_t)(LAYER * HH + h) * 12;
        float e = (j == 0) ? em.x : (j == 1) ? em.y : (j == 2) ? em.z : em.w;
#pragma unroll
        for (int c = 0; c < 12; ++c) p[c] = fmaf(e, wrow[c], p[c]);
    }
#pragma unroll
    for (int c = 0; c < 12; ++c) {
        p[c] += __shfl_xor_sync(0xffffffffu, p[c], 16);
        p[c] += __shfl_xor_sync(0xffffffffu, p[c], 8);
        p[c] += __shfl_xor_sync(0xffffffffu, p[c], 4);
        p[c] += __shfl_xor_sync(0xffffffffu, p[c], 2);
        p[c] += __shfl_xor_sync(0xffffffffu, p[c], 1);
    }

    if (l == 0) {
        float atoms[12];
#pragma unroll
        for (int c = 0; c < 12; ++c) atoms[c] = p[c] + ba[LAYER * 12 + c];

        const float* a = g_acc + (size_t)n * 16;
        float den0 = a[0];
        float den1 = a[1];
        float inv0 = (den0 != 0.0f) ? (1.0f / den0) : 0.0f;
        float inv1 = (den1 != 0.0f) ? (1.0f / den1) : 0.0f;

        // node dither (key k2, partitionable stream) on the NORMALIZED R_unc,
        // fp32 add (reference semantics), then fp64 polar
        unsigned k1a, k1b, k2a, k2b;
        derive_keys(k1a, k1b, k2a, k2b);
        double Rn[9];
#pragma unroll
        for (int j = 0; j < 9; ++j) {
            float nz = bits_to_normal(tf_bits(k2a, k2b, (unsigned)n * 9u + (unsigned)j));
            float m2 = a[5 + j] * inv1 + DITHER * nz;
            Rn[j] = (double)m2;
        }

        float Ravg[9];
        polar3d(Rn, Ravg);
        float tavg[3] = {a[2]*inv0, a[3]*inv0, a[4]*inv0};

        float o[12];
#pragma unroll
        for (int aa = 0; aa < 4; ++aa)
#pragma unroll
            for (int i = 0; i < 3; ++i)
                o[aa*3 + i] = Ravg[i*3+0]*atoms[aa*3+0] + Ravg[i*3+1]*atoms[aa*3+1]
                            + Ravg[i*3+2]*atoms[aa*3+2] + tavg[i];
        float4* xo = reinterpret_cast<float4*>(X + (size_t)n * 12);
        xo[0] = make_float4(o[0], o[1], o[2],  o[3]);
        xo[1] = make_float4(o[4], o[5], o[6],  o[7]);
        xo[2] = make_float4(o[8], o[9], o[10], o[11]);
    }
}

extern "C" void kernel_launch(void* const* d_in, const int* in_sizes, int n_in,
                              void* d_out, int out_size) {
    const float* R        = (const float*)d_in[1];
    const float* t        = (const float*)d_in[2];
    const float* node_emb = (const float*)d_in[3];
    const float* edge_emb = (const float*)d_in[4];
    const int*   eidx     = (const int*)  d_in[5];
    const float* Wl = (const float*)d_in[7];
    const float* bl = (const float*)d_in[8];
    const float* Wq = (const float*)d_in[9];
    const float* bq = (const float*)d_in[10];
    const float* Wt = (const float*)d_in[11];
    const float* bt = (const float*)d_in[12];
    const float* Ws = (const float*)d_in[13];
    const float* bs = (const float*)d_in[14];
    const float* Wa = (const float*)d_in[15];
    const float* ba = (const float*)d_in[16];
    float* X = (float*)d_out;

    zero_acc_kernel<<<(NN * 16 + 255) / 256, 256>>>();
    edge_kernel<<<EE / 512, 256>>>(edge_emb, eidx, R, t, Ws, bs, Wq, bq, Wt, bt, Wl, bl);
    node_kernel<<<NN / 8, 256>>>(node_emb, Wa, ba, X);
}

// round 11
// speedup vs baseline: 3.7595x; 3.7595x over previous
#include <cuda_runtime.h>
#include <math.h>

#define NN 20000
#define EE 640000
#define HH 128
#define LAYER 2
#define DSCALE 10.0f
#define DITHER 1e-4f

// per-node accumulator: [den0, den1, t0,t1,t2, R00..R22, pad, pad] = 16 floats
__device__ float g_acc[NN * 16];

// ---------- f32x2 helpers ----------
__device__ __forceinline__ void fma2(unsigned long long &acc, unsigned long long a, unsigned long long b) {
    asm("fma.rn.f32x2 %0, %1, %2, %0;" : "+l"(acc) : "l"(a), "l"(b));
}
__device__ __forceinline__ unsigned long long pack2(float x) {
    unsigned long long r; asm("mov.b64 %0, {%1, %1};" : "=l"(r) : "f"(x)); return r;
}
__device__ __forceinline__ float2 unpk(unsigned long long v) {
    float2 r; asm("mov.b64 {%0, %1}, %2;" : "=f"(r.x), "=f"(r.y) : "l"(v)); return r;
}

// ---------- jax threefry2x32 (20 rounds), constexpr-evaluable ----------
struct TF2 { unsigned x, y; };
__host__ __device__ constexpr unsigned rotl(unsigned x, int r) {
    return (x << r) | (x >> (32 - r));
}
__host__ __device__ constexpr TF2 tf(unsigned k0, unsigned k1, unsigned c0, unsigned c1) {
    unsigned ks2 = k0 ^ k1 ^ 0x1BD11BDAu;
    unsigned x0 = c0 + k0, x1 = c1 + k1;
#define TFR(r) { x0 += x1; x1 = rotl(x1, r); x1 ^= x0; }
    TFR(13) TFR(15) TFR(26) TFR(6)
    x0 += k1;  x1 += ks2 + 1u;
    TFR(17) TFR(29) TFR(16) TFR(24)
    x0 += ks2; x1 += k0 + 2u;
    TFR(13) TFR(15) TFR(26) TFR(6)
    x0 += k0;  x1 += k1 + 3u;
    TFR(17) TFR(29) TFR(16) TFR(24)
    x0 += k1;  x1 += ks2 + 4u;
    TFR(13) TFR(15) TFR(26) TFR(6)
    x0 += ks2; x1 += k0 + 5u;
#undef TFR
    return TF2{x0, x1};
}
// jax PARTITIONABLE scheme (default since 0.4.36):
//   fold_in: f = TF(key, (0, data));  split subkey i = TF(f, (0, i))
//   random_bits 32-bit: counter (0, idx), bits = o0 ^ o1
// keys constant-folded at compile time: base=(0,42), fold 2, split [k1, k2]
constexpr TF2 KF = tf(0u, 42u, 0u, 2u);
constexpr TF2 K1 = tf(KF.x, KF.y, 0u, 0u);
constexpr TF2 K2 = tf(KF.x, KF.y, 0u, 1u);

__device__ __forceinline__ unsigned tf_bits(unsigned k0, unsigned k1, unsigned idx) {
    TF2 o = tf(k0, k1, 0u, idx);
    return o.x ^ o.y;
}
// jax: u01 = bitcast((bits>>9)|0x3f800000)-1; r = max(lo, u01*2+lo); sqrt(2)*erfinv(r)
__device__ __forceinline__ float bits_to_normal(unsigned bits) {
    const float lo = -0.99999994f;
    float u01 = __uint_as_float((bits >> 9) | 0x3f800000u) - 1.0f;
    float r = fmaxf(lo, fmaf(u01, 2.0f, lo));
    return 1.41421356f * erfinvf(r);
}

// ---------- fp32 scaled-Newton polar factor with reference's det fix ----------
// IT total iterations, SC of them Higham-Frobenius-scaled. Fast-math intrinsics:
// Newton self-corrects, final plain iterations contract quadratically.
template <int IT, int SC>
__device__ void polar3t(const float M[9], float R[9]) {
    float X[9];
#pragma unroll
    for (int i = 0; i < 9; ++i) X[i] = M[i];
#pragma unroll
    for (int it = 0; it < IT; ++it) {
        float c0 = X[4]*X[8] - X[5]*X[7];
        float c1 = X[5]*X[6] - X[3]*X[8];
        float c2 = X[3]*X[7] - X[4]*X[6];
        float c3 = X[2]*X[7] - X[1]*X[8];
        float c4 = X[0]*X[8] - X[2]*X[6];
        float c5 = X[1]*X[6] - X[0]*X[7];
        float c6 = X[1]*X[5] - X[2]*X[4];
        float c7 = X[2]*X[3] - X[0]*X[5];
        float c8 = X[0]*X[4] - X[1]*X[3];
        float det = X[0]*c0 + X[1]*c1 + X[2]*c2;
        float rdet = (fabsf(det) > 1e-30f) ? __fdividef(1.0f, det) : 0.0f;
        float ha, hb;
        if (it < SC) {
            float a = X[0]*X[0]+X[1]*X[1]+X[2]*X[2]+X[3]*X[3]+X[4]*X[4]
                    + X[5]*X[5]+X[6]*X[6]+X[7]*X[7]+X[8]*X[8];
            float b = (c0*c0+c1*c1+c2*c2+c3*c3+c4*c4+c5*c5+c6*c6+c7*c7+c8*c8) * rdet * rdet;
            float r = __fdividef(b, a + 1e-30f);
            float g = __frsqrt_rn(__frsqrt_rn(r));   // r^(1/4)
            g = fminf(fmaxf(g, 1e-5f), 1e5f);        // NaN-safe clamp
            ha = 0.5f * g;
            hb = __fdividef(0.5f * rdet, g);
        } else {
            ha = 0.5f;
            hb = 0.5f * rdet;
        }
        X[0]=ha*X[0]+hb*c0; X[1]=ha*X[1]+hb*c1; X[2]=ha*X[2]+hb*c2;
        X[3]=ha*X[3]+hb*c3; X[4]=ha*X[4]+hb*c4; X[5]=ha*X[5]+hb*c5;
        X[6]=ha*X[6]+hb*c6; X[7]=ha*X[7]+hb*c7; X[8]=ha*X[8]+hb*c8;
    }
    float d = X[0]*(X[4]*X[8]-X[5]*X[7]) - X[1]*(X[3]*X[8]-X[5]*X[6]) + X[2]*(X[3]*X[7]-X[4]*X[6]);
#pragma unroll
    for (int i = 0; i < 9; ++i) R[i] = X[i];
    R[2] *= d; R[5] *= d; R[8] *= d;   // scale last column by det (reference behavior)
}

__global__ void zero_acc_kernel() {
    int i = blockIdx.x * 256 + threadIdx.x;
    if (i < NN * 16) g_acc[i] = 0.0f;
}

// ---------- edge scalar tail ----------
__device__ __forceinline__ void do_edge(
    int e, const unsigned long long acc[8], const float* sB,
    const int* __restrict__ eidx, const float* __restrict__ R, const float* __restrict__ t)
{
    float out[16];
#pragma unroll
    for (int m = 0; m < 8; ++m) {
        float2 v = unpk(acc[m]);
        out[2*m]   = v.x + sB[2*m];
        out[2*m+1] = v.y + sB[2*m+1];
    }
    float s0 = __fdividef(1.0f, 1.0f + __expf(-out[0]));
    float s1 = __fdividef(1.0f, 1.0f + __expf(-out[1]));
    int src = eidx[e];
    int dst = eidx[EE + e];
    float Rs[9], Rd[9];
#pragma unroll
    for (int i = 0; i < 9; ++i) { Rs[i] = R[src*9 + i]; Rd[i] = R[dst*9 + i]; }
    float dt0 = t[src*3+0] - t[dst*3+0];
    float dt1 = t[src*3+1] - t[dst*3+1];
    float dt2 = t[src*3+2] - t[dst*3+2];

    // dither noise, partitionable stream: element idx = e*9 + j (bit-exact jax)
    float nz[9];
#pragma unroll
    for (int j = 0; j < 9; ++j)
        nz[j] = bits_to_normal(tf_bits(K1.x, K1.y, (unsigned)e * 9u + (unsigned)j));

    // q = s0 * (Rd^T Rs) + (1-s0) * Lq + eps*noise
    float q[9];
#pragma unroll
    for (int i = 0; i < 3; ++i)
#pragma unroll
        for (int k = 0; k < 3; ++k) {
            float rji = Rd[0*3+i]*Rs[0*3+k] + Rd[1*3+i]*Rs[1*3+k] + Rd[2*3+i]*Rs[2*3+k];
            q[i*3+k] = s0 * rji + (1.0f - s0) * out[2 + i*3 + k] + DITHER * nz[i*3+k];
        }
    float tts[3];
#pragma unroll
    for (int i = 0; i < 3; ++i) {
        float tji = Rd[0*3+i]*dt0 + Rd[1*3+i]*dt1 + Rd[2*3+i]*dt2;
        tts[i] = s1 * tji + (1.0f - s1) * DSCALE * out[11 + i];
    }
    float Rts[9];
    polar3t<6, 3>(q, Rts);

    float e0l = __expf(out[14]);   // softmax weight for t (no max-shift; logits ~N(0,1))
    float e1l = __expf(out[15]);   // softmax weight for R

    float* ap = g_acc + (size_t)src * 16;
    atomicAdd(ap + 0, e0l);
    atomicAdd(ap + 1, e1l);
#pragma unroll
    for (int i = 0; i < 3; ++i) {
        float tp = t[dst*3+i] + Rd[i*3+0]*tts[0] + Rd[i*3+1]*tts[1] + Rd[i*3+2]*tts[2];
        atomicAdd(ap + 2 + i, e0l * tp);
    }
#pragma unroll
    for (int i = 0; i < 3; ++i)
#pragma unroll
        for (int k = 0; k < 3; ++k) {
            float rp = Rd[i*3+0]*Rts[0*3+k] + Rd[i*3+1]*Rts[1*3+k] + Rd[i*3+2]*Rts[2*3+k];
            atomicAdd(ap + 5 + i*3 + k, e1l * rp);
        }
}

// ---------- edge kernel: 512 consecutive edges per block of 256 threads ----------
__global__ void __launch_bounds__(256) edge_kernel(
    const float* __restrict__ emb, const int* __restrict__ eidx,
    const float* __restrict__ R,  const float* __restrict__ t,
    const float* __restrict__ Ws, const float* __restrict__ bs_,
    const float* __restrict__ Wq, const float* __restrict__ bq_,
    const float* __restrict__ Wt, const float* __restrict__ bt_,
    const float* __restrict__ Wl, const float* __restrict__ bl_)
{
    __shared__ float sW[HH][16];     // fused weights, cols: [Ws(2)|Wq(9)|Wt(3)|Wl(2)]
    __shared__ float sB[16];
    __shared__ float sS[16][514];    // transposed emb chunk

    const int tid = threadIdx.x;
    for (int i = tid; i < HH * 16; i += 256) {
        int h = i >> 4, c = i & 15;
        int hb = LAYER * HH + h;
        float w;
        if (c < 2)       w = Ws[hb*2 + c];
        else if (c < 11) w = Wq[hb*9 + (c - 2)];
        else if (c < 14) w = Wt[hb*3 + (c - 11)];
        else             w = Wl[hb*2 + (c - 14)];
        sW[h][c] = w;
    }
    if (tid < 16) {
        int c = tid; float b;
        if (c < 2)       b = bs_[LAYER*2 + c];
        else if (c < 11) b = bq_[LAYER*9 + c - 2];
        else if (c < 14) b = bt_[LAYER*3 + c - 11];
        else             b = bl_[LAYER*2 + c - 14];
        sB[c] = b;
    }

    const int e0 = blockIdx.x * 512;
    const float4* emb4 = reinterpret_cast<const float4*>(emb);

    unsigned long long accA[8], accB[8];
#pragma unroll
    for (int m = 0; m < 8; ++m) { accA[m] = 0ull; accB[m] = 0ull; }

    for (int c = 0; c < 8; ++c) {              // 8 chunks of 16 H-dims
        __syncthreads();
#pragma unroll
        for (int k = 0; k < 8; ++k) {
            int idx = tid + 256 * k;           // 0..2047 = 512 edges x 4 float4
            int de  = idx >> 2;
            int d4  = idx & 3;
            float4 v = emb4[(size_t)(e0 + de) * 32 + c * 4 + d4];
            int row = d4 * 4;
            sS[row + 0][de] = v.x;
            sS[row + 1][de] = v.y;
            sS[row + 2][de] = v.z;
            sS[row + 3][de] = v.w;
        }
        __syncthreads();
#pragma unroll
        for (int dh = 0; dh < 16; ++dh) {
            int h = c * 16 + dh;
            unsigned long long pa = pack2(sS[dh][tid]);
            unsigned long long pb = pack2(sS[dh][tid + 256]);
            const ulonglong2* wr = reinterpret_cast<const ulonglong2*>(&sW[h][0]);
#pragma unroll
            for (int p = 0; p < 4; ++p) {
                ulonglong2 w = wr[p];
                fma2(accA[2*p],   pa, w.x);
                fma2(accA[2*p+1], pa, w.y);
                fma2(accB[2*p],   pb, w.x);
                fma2(accB[2*p+1], pb, w.y);
            }
        }
    }

    do_edge(e0 + tid,       accA, sB, eidx, R, t);
    do_edge(e0 + tid + 256, accB, sB, eidx, R, t);
}

// ---------- node kernel: one warp per node ----------
__global__ void __launch_bounds__(256) node_kernel(
    const float* __restrict__ node_emb,
    const float* __restrict__ Wa, const float* __restrict__ ba,
    float* __restrict__ X)
{
    int n = blockIdx.x * 8 + (threadIdx.x >> 5);
    int l = threadIdx.x & 31;
    const float4* em4 = reinterpret_cast<const float4*>(node_emb);
    float4 em = em4[(size_t)n * 32 + l];

    float p[12];
#pragma unroll
    for (int c = 0; c < 12; ++c) p[c] = 0.0f;
#pragma unroll
    for (int j = 0; j < 4; ++j) {
        int h = 4 * l + j;
        const float* wrow = Wa + (size_t)(LAYER * HH + h) * 12;
        float e = (j == 0) ? em.x : (j == 1) ? em.y : (j == 2) ? em.z : em.w;
#pragma unroll
        for (int c = 0; c < 12; ++c) p[c] = fmaf(e, wrow[c], p[c]);
    }
#pragma unroll
    for (int c = 0; c < 12; ++c) {
        p[c] += __shfl_xor_sync(0xffffffffu, p[c], 16);
        p[c] += __shfl_xor_sync(0xffffffffu, p[c], 8);
        p[c] += __shfl_xor_sync(0xffffffffu, p[c], 4);
        p[c] += __shfl_xor_sync(0xffffffffu, p[c], 2);
        p[c] += __shfl_xor_sync(0xffffffffu, p[c], 1);
    }

    if (l == 0) {
        float atoms[12];
#pragma unroll
        for (int c = 0; c < 12; ++c) atoms[c] = p[c] + ba[LAYER * 12 + c];

        const float* a = g_acc + (size_t)n * 16;
        float den0 = a[0];
        float den1 = a[1];
        float inv0 = (den0 != 0.0f) ? (1.0f / den0) : 0.0f;
        float inv1 = (den1 != 0.0f) ? (1.0f / den1) : 0.0f;

        // node dither (key K2, partitionable stream) on the NORMALIZED R_unc (fp32),
        // then fp32 scaled-Newton polar (det sign stable at fp32 for kappa<=1e4)
        float Rn[9];
#pragma unroll
        for (int j = 0; j < 9; ++j) {
            float nz = bits_to_normal(tf_bits(K2.x, K2.y, (unsigned)n * 9u + (unsigned)j));
            Rn[j] = a[5 + j] * inv1 + DITHER * nz;
        }

        float Ravg[9];
        polar3t<9, 4>(Rn, Ravg);
        float tavg[3] = {a[2]*inv0, a[3]*inv0, a[4]*inv0};

        float o[12];
#pragma unroll
        for (int aa = 0; aa < 4; ++aa)
#pragma unroll
            for (int i = 0; i < 3; ++i)
                o[aa*3 + i] = Ravg[i*3+0]*atoms[aa*3+0] + Ravg[i*3+1]*atoms[aa*3+1]
                            + Ravg[i*3+2]*atoms[aa*3+2] + tavg[i];
        float4* xo = reinterpret_cast<float4*>(X + (size_t)n * 12);
        xo[0] = make_float4(o[0], o[1], o[2],  o[3]);
        xo[1] = make_float4(o[4], o[5], o[6],  o[7]);
        xo[2] = make_float4(o[8], o[9], o[10], o[11]);
    }
}

extern "C" void kernel_launch(void* const* d_in, const int* in_sizes, int n_in,
                              void* d_out, int out_size) {
    const float* R        = (const float*)d_in[1];
    const float* t        = (const float*)d_in[2];
    const float* node_emb = (const float*)d_in[3];
    const float* edge_emb = (const float*)d_in[4];
    const int*   eidx     = (const int*)  d_in[5];
    const float* Wl = (const float*)d_in[7];
    const float* bl = (const float*)d_in[8];
    const float* Wq = (const float*)d_in[9];
    const float* bq = (const float*)d_in[10];
    const float* Wt = (const float*)d_in[11];
    const float* bt = (const float*)d_in[12];
    const float* Ws = (const float*)d_in[13];
    const float* bs = (const float*)d_in[14];
    const float* Wa = (const float*)d_in[15];
    const float* ba = (const float*)d_in[16];
    float* X = (float*)d_out;

    zero_acc_kernel<<<(NN * 16 + 255) / 256, 256>>>();
    edge_kernel<<<EE / 512, 256>>>(edge_emb, eidx, R, t, Ws, bs, Wq, bq, Wt, bt, Wl, bl);
    node_kernel<<<NN / 8, 256>>>(node_emb, Wa, ba, X);
}